// round 16
// baseline (speedup 1.0000x reference)
#include <cuda_runtime.h>
#include <cuda_fp16.h>
#include <math.h>
#include <stdint.h>

#define FEA 512
#define DKH 64
#define NH  8
#define BB  4
#define LL  2048
#define MM  (BB*LL)          // 8192
#define HID (4*FEA)          // 2048

// ---------------------------------------------------------------------------
// Scratch
// ---------------------------------------------------------------------------
__device__ float g_z   [MM*FEA];
__device__ float g_zn32[MM*FEA];
__device__ float g_f   [MM*FEA];
__device__ uint32_t g_mb[BB*LL*(LL/32)];

__device__ __align__(256) __half g_xin16 [3*MM*FEA];
__device__ __align__(256) __half g_qkv16 [3*MM*FEA];
__device__ __align__(256) __half g_wqkv16[3*FEA*FEA];
__device__ __align__(256) __half g_ao16[MM*FEA];
__device__ __align__(256) __half g_zn16[MM*FEA];
__device__ __align__(256) __half g_h16 [MM*HID];
__device__ __align__(256) __half g_wo16[FEA*FEA];
__device__ __align__(256) __half g_w116[FEA*HID];
__device__ __align__(256) __half g_w216[HID*FEA];

struct Ptr3f { const float* p[3]; };
struct ActJobs {
    const float* a0; const float* a1; const float* a2; __half* xin;
    const float* wq; const float* wk; const float* wv; __half* wqkv;
};
struct WJobs {
    const float* wo; const float* w1; const float* w2;
    __half* hwo; __half* hw1; __half* hw2;
};

#define NWORDS   (BB*LL*LL/32)
#define NB_MASK  (NWORDS/256)
#define NA4      (MM*FEA/4)
#define NB_ACT   (3*NA4/1024)
#define NW4      (FEA*FEA/4)
#define NB_WQKV  (3*NW4/1024)
#define NF0      (FEA*FEA/4)
#define NF01     (FEA*FEA/4 + FEA*HID/4)
#define NFTOT    (FEA*FEA/4 + FEA*HID/4 + HID*FEA/4)
#define NB_WFLAT (NFTOT/1024)

// log2e / sqrt(dk): folded into Q at the projection epilogue
#define QSC 0.18033688011112042f

// ---------------------------------------------------------------------------
// helpers
// ---------------------------------------------------------------------------
__device__ __forceinline__ uint32_t cvta_s(const void* p) {
    uint32_t a;
    asm("{ .reg .u64 t; cvta.to.shared.u64 t, %1; cvt.u32.u64 %0, t; }"
        : "=r"(a) : "l"(p));
    return a;
}
__device__ __forceinline__ void cp16(uint32_t dst, const void* src) {
    asm volatile("cp.async.cg.shared.global [%0], [%1], 16;" :: "r"(dst), "l"(src));
}
#define CP_COMMIT() asm volatile("cp.async.commit_group;")
#define CP_WAIT(n)  asm volatile("cp.async.wait_group %0;" :: "n"(n))

__device__ __forceinline__ void ldsm4(uint32_t r[4], uint32_t addr) {
    asm volatile("ldmatrix.sync.aligned.m8n8.x4.shared.b16 {%0,%1,%2,%3}, [%4];"
        : "=r"(r[0]), "=r"(r[1]), "=r"(r[2]), "=r"(r[3]) : "r"(addr));
}
__device__ __forceinline__ void ldsm4t(uint32_t r[4], uint32_t addr) {
    asm volatile("ldmatrix.sync.aligned.m8n8.x4.trans.shared.b16 {%0,%1,%2,%3}, [%4];"
        : "=r"(r[0]), "=r"(r[1]), "=r"(r[2]), "=r"(r[3]) : "r"(addr));
}
__device__ __forceinline__ void mma16816(float c[4], const uint32_t a[4],
                                         uint32_t b0, uint32_t b1) {
    asm volatile(
        "mma.sync.aligned.m16n8k16.row.col.f32.f16.f16.f32 "
        "{%0,%1,%2,%3}, {%4,%5,%6,%7}, {%8,%9}, {%0,%1,%2,%3};"
        : "+f"(c[0]), "+f"(c[1]), "+f"(c[2]), "+f"(c[3])
        : "r"(a[0]), "r"(a[1]), "r"(a[2]), "r"(a[3]), "r"(b0), "r"(b1));
}
__device__ __forceinline__ uint32_t ex2h2(uint32_t x) {
    uint32_t r;
    asm("ex2.approx.f16x2 %0, %1;" : "=r"(r) : "r"(x));
    return r;
}
__device__ __forceinline__ uint32_t packh2(float lo, float hi) {
    __half2 h = __floats2half2_rn(lo, hi);
    return *reinterpret_cast<uint32_t*>(&h);
}
__device__ __forceinline__ void f2h_one(const float* s, __half* d, int off) {
    float4 v = ((const float4*)s)[off];
    ((__half2*)d)[2*off]   = __floats2half2_rn(v.x, v.y);
    ((__half2*)d)[2*off+1] = __floats2half2_rn(v.z, v.w);
}

// ---------------------------------------------------------------------------
// pre-pass kernels
// ---------------------------------------------------------------------------
__global__ __launch_bounds__(256)
void pre_mask(const int4* __restrict__ mask, uint32_t* __restrict__ mbits)
{
    int T = blockIdx.x * 256 + threadIdx.x;
    const int4* p = mask + (size_t)T * 8;
    uint32_t w = 0;
    #pragma unroll
    for (int k = 0; k < 8; k++) {
        int4 v = p[k];
        uint32_t n = umin((uint32_t)v.x, 1u)
                   | (umin((uint32_t)v.y, 1u) << 1)
                   | (umin((uint32_t)v.z, 1u) << 2)
                   | (umin((uint32_t)v.w, 1u) << 3);
        w |= n << (k * 4);
    }
    mbits[T] = w;
}

__global__ __launch_bounds__(256)
void pre_acts(ActJobs j)
{
    const int bid = blockIdx.x, tid = threadIdx.x;
    if (bid < NB_ACT) {
        int base = bid * 1024;
        int z = base / NA4;
        const float* s = z == 0 ? j.a0 : (z == 1 ? j.a1 : j.a2);
        __half* d = j.xin + (size_t)z * NA4 * 4;
        int lb = base - z * NA4;
        #pragma unroll
        for (int k = 0; k < 4; k++)
            f2h_one(s, d, lb + tid + k * 256);
    } else {
        int base = (bid - NB_ACT) * 1024;
        int z = base / NW4;
        const float* s = z == 0 ? j.wq : (z == 1 ? j.wk : j.wv);
        __half* d = j.wqkv + (size_t)z * NW4 * 4;
        int lb = base - z * NW4;
        #pragma unroll
        for (int k = 0; k < 4; k++)
            f2h_one(s, d, lb + tid + k * 256);
    }
}

__global__ __launch_bounds__(256)
void pre_wflat(WJobs j)
{
    const int tid = threadIdx.x;
    int base = blockIdx.x * 1024;
    const float* s; __half* d; int lb;
    if (base < NF0)       { s = j.wo; d = j.hwo; lb = base; }
    else if (base < NF01) { s = j.w1; d = j.hw1; lb = base - NF0; }
    else                  { s = j.w2; d = j.hw2; lb = base - NF01; }
    #pragma unroll
    for (int k = 0; k < 4; k++)
        f2h_one(s, d, lb + tid + k * 256);
}

// ---------------------------------------------------------------------------
// fp16 GEMM: 3-stage cp.async + ldmatrix, BK=64, 512 threads, warp tile 32x32.
// 16 warps/CTA, 2 CTAs/SM -> 32 warps/SM. QS: scale z==0 output by QSC.
// ---------------------------------------------------------------------------
#define GEMM_SMEM_BYTES (3*32768)

template<int EPI, int OUTH, int TRIPLE>
__global__ __launch_bounds__(512, 2)
void gemm_f16(const __half* __restrict__ A, const __half* __restrict__ W,
              const float* __restrict__ bias, const float* __restrict__ res,
              void* __restrict__ Cv, int M, int N, int K, Ptr3f b3)
{
    extern __shared__ __align__(16) uint8_t smg[];
    const uint32_t sT = cvta_s(smg);

    __half* Ch = (__half*)Cv;
    float*  Cf = (float*)Cv;
    float oscale = 1.0f;
    if (TRIPLE) {
        const int z = blockIdx.z;
        A += (size_t)z * M * K;
        W += (size_t)z * K * N;
        Ch += (size_t)z * M * N;
        bias = b3.p[z];
        if (z == 0) oscale = QSC;
    }

    const int tid = threadIdx.x, lane = tid & 31, wid = tid >> 5;
    const int warpRow = wid & 3;        // 4 x 32 rows
    const int warpCol = wid >> 2;       // 4 x 32 cols
    const int m0 = blockIdx.y * 128, n0 = blockIdx.x * 128;
    const int g = lane >> 2, tg = lane & 3;

    const int KT = K >> 6;
    float acc[2][4][4] = {};

    // loader: A 1024 chunks (128 rows x 8), B 1024 chunks (64 rows x 16); 512 thr
#define GI(st, ck) do { const int k0_ = (ck) << 6;                                \
    _Pragma("unroll")                                                             \
    for (int i_ = 0; i_ < 2; i_++) {                                              \
        int ia_ = tid + i_ * 512;                                                 \
        int ra_ = ia_ >> 3, ca_ = ia_ & 7;                                        \
        cp16(sT + (st)*32768 + ra_*128 + (uint32_t)((ca_ ^ (ra_ & 7)) << 4),      \
             A + (size_t)(m0 + ra_)*K + k0_ + ca_*8);                             \
        int rb_ = ia_ >> 4, cb_ = ia_ & 15;                                       \
        cp16(sT + (st)*32768 + 16384 + rb_*256 + (uint32_t)((cb_ ^ (rb_ & 7)) << 4), \
             W + (size_t)(k0_ + rb_)*N + n0 + cb_*8);                             \
    } } while (0)

    GI(0, 0); CP_COMMIT();
    GI(1, 1); CP_COMMIT();

    const int arow = warpRow*32 + (lane & 15);       // + mf*16
    const int alo  = lane >> 4;
    const int brow = lane & 15;
    const int bccb = warpCol*4 + (lane >> 4);

    int cur = 0;
    for (int kt = 0; kt < KT; kt++) {
        CP_WAIT(1);
        __syncthreads();
        if (kt + 2 < KT) { int st = cur >= 1 ? cur - 1 : 2; GI(st, kt + 2); }
        CP_COMMIT();
        const uint32_t Ast = sT + cur * 32768;
        const uint32_t Bst = Ast + 16384;

        #pragma unroll
        for (int kc = 0; kc < 4; kc++) {
            uint32_t af[2][4];
            #pragma unroll
            for (int mf = 0; mf < 2; mf++) {
                int r = arow + mf * 16;
                ldsm4(af[mf], Ast + r*128 + (((kc*2 + alo) ^ (r & 7)) << 4));
            }
            uint32_t bf[4][2];
            #pragma unroll
            for (int p = 0; p < 2; p++) {
                int r = kc*16 + brow;
                uint32_t cc = bccb + p*2;
                uint32_t t4[4];
                ldsm4t(t4, Bst + r*256 + ((cc ^ (r & 7)) << 4));
                bf[2*p][0] = t4[0]; bf[2*p][1] = t4[1];
                bf[2*p+1][0] = t4[2]; bf[2*p+1][1] = t4[3];
            }
            #pragma unroll
            for (int mf = 0; mf < 2; mf++)
                #pragma unroll
                for (int nf = 0; nf < 4; nf++)
                    mma16816(acc[mf][nf], af[mf], bf[nf][0], bf[nf][1]);
        }
        cur = cur < 2 ? cur + 1 : 0;
    }
#undef GI

    #pragma unroll
    for (int mf = 0; mf < 2; mf++) {
        int row = m0 + warpRow*32 + mf*16 + g;
        #pragma unroll
        for (int nf = 0; nf < 4; nf++) {
            int col = n0 + warpCol*32 + nf*8 + 2*tg;
            float2 bi = *(const float2*)&bias[col];
            float o0 = acc[mf][nf][0] + bi.x;
            float o1 = acc[mf][nf][1] + bi.y;
            float o2 = acc[mf][nf][2] + bi.x;
            float o3 = acc[mf][nf][3] + bi.y;
            if (EPI == 1) {
                o0 = 0.5f*o0*(1.f+erff(o0*0.70710678118654752f));
                o1 = 0.5f*o1*(1.f+erff(o1*0.70710678118654752f));
                o2 = 0.5f*o2*(1.f+erff(o2*0.70710678118654752f));
                o3 = 0.5f*o3*(1.f+erff(o3*0.70710678118654752f));
            } else if (EPI == 2) {
                float2 r0 = *(const float2*)&res[(size_t)row*N + col];
                float2 r1 = *(const float2*)&res[(size_t)(row+8)*N + col];
                o0 += r0.x; o1 += r0.y; o2 += r1.x; o3 += r1.y;
            }
            if (TRIPLE) { o0 *= oscale; o1 *= oscale; o2 *= oscale; o3 *= oscale; }
            if (OUTH) {
                *(__half2*)&Ch[(size_t)row*N + col]     = __floats2half2_rn(o0, o1);
                *(__half2*)&Ch[(size_t)(row+8)*N + col] = __floats2half2_rn(o2, o3);
            } else {
                float2 w0 = {o0, o1}, w1 = {o2, o3};
                *(float2*)&Cf[(size_t)row*N + col]     = w0;
                *(float2*)&Cf[(size_t)(row+8)*N + col] = w1;
            }
        }
    }
}

// ---------------------------------------------------------------------------
// fp16 flash attention — unchanged from R15 (Q pre-scaled, shift-free softmax)
// ---------------------------------------------------------------------------
#define ATT_SMEM_BYTES (16384 + 2*32768)
#define ONESH2 0x3C003C00u

__global__ __launch_bounds__(256, 2)
void attn_f16(const __half* __restrict__ Q, const __half* __restrict__ Kg,
              const __half* __restrict__ Vg, const uint32_t* __restrict__ mbits,
              __half* __restrict__ O)
{
    extern __shared__ __align__(16) uint8_t smb[];
    const uint32_t sQ  = cvta_s(smb);
    const uint32_t sKV = sQ + 16384;

    const int q0 = blockIdx.x * 128;
    const int h  = blockIdx.y;
    const int b  = blockIdx.z;
    const int tid = threadIdx.x, lane = tid & 31, wid = tid >> 5;
    const int g = lane >> 2, tg = lane & 3;
    const int row = wid*16 + g;

    const __half* Qb = Q + (size_t)(b*LL + q0)*FEA + h*DKH;
    const __half* Kb = Kg + (size_t)(b*LL)*FEA + h*DKH;
    const __half* Vb = Vg + (size_t)(b*LL)*FEA + h*DKH;

    #pragma unroll
    for (int i = 0; i < 4; i++) {
        int idx = tid + i*256;
        int r = idx >> 3, c = idx & 7;
        cp16(sQ + r*128 + ((c ^ (r&7)) << 4), Qb + (size_t)r*FEA + c*8);
    }
    CP_COMMIT();

#define AI(st, k0_) do { _Pragma("unroll")                                      \
    for (int i_ = 0; i_ < 4; i_++) {                                            \
        int idx_ = tid + i_*256;                                                \
        int r_ = idx_ >> 3, c_ = idx_ & 7;                                      \
        uint32_t off_ = r_*128 + ((c_ ^ (r_&7)) << 4);                          \
        cp16(sKV + (st)*32768 + off_,         Kb + (size_t)((k0_)+r_)*FEA + c_*8); \
        cp16(sKV + (st)*32768 + 16384 + off_, Vb + (size_t)((k0_)+r_)*FEA + c_*8); \
    } } while (0)

    AI(0, 0); CP_COMMIT();
    CP_WAIT(1);
    __syncthreads();

    uint32_t qf[4][4];
    {
        int r = wid*16 + (lane & 15);
        int lo = lane >> 4;
        #pragma unroll
        for (int kc = 0; kc < 4; kc++)
            ldsm4(qf[kc], sQ + r*128 + (((kc*2 + lo) ^ (r&7)) << 4));
    }

    float oacc[8][4] = {};
    float lacc[4] = {};
    const uint32_t* mb0 = mbits + (size_t)(b*LL + q0 + row) * (LL/32);
    const uint32_t* mb1 = mb0 + 8 * (LL/32);

    const int krow = ((lane>>4)<<3) | (lane & 7);
    const int ksel = (lane>>3) & 1;
    const int vrow = (((lane>>3)&1)<<3) | (lane&7);
    const int vsel = lane >> 4;

    for (int t = 0; t < LL/128; t++) {
        uint4 w0 = *(const uint4*)(mb0 + 4*t);
        uint4 w1 = *(const uint4*)(mb1 + 4*t);

        CP_WAIT(0);
        __syncthreads();
        if (t + 1 < LL/128) AI((t+1) & 1, (t+1)*128);
        CP_COMMIT();
        const uint32_t stBase = sKV + (t&1)*32768;

        #pragma unroll
        for (int hh = 0; hh < 2; hh++) {
            const uint32_t Kst = stBase + hh*8192;
            const uint32_t Vst = stBase + 16384 + hh*8192;
            const uint64_t u0 = hh ? ((uint64_t)w0.z | ((uint64_t)w0.w << 32))
                                   : ((uint64_t)w0.x | ((uint64_t)w0.y << 32));
            const uint64_t u1 = hh ? ((uint64_t)w1.z | ((uint64_t)w1.w << 32))
                                   : ((uint64_t)w1.x | ((uint64_t)w1.y << 32));

            #pragma unroll
            for (int pc = 0; pc < 4; pc++) {
                float s0[4] = {}, s1[4] = {};
                #pragma unroll
                for (int kc = 0; kc < 4; kc++) {
                    int r = pc*16 + krow;
                    uint32_t cc = kc*2 + ksel;
                    uint32_t t4[4];
                    ldsm4(t4, Kst + r*128 + ((cc ^ (r&7)) << 4));
                    mma16816(s0, qf[kc], t4[0], t4[1]);
                    mma16816(s1, qf[kc], t4[2], t4[3]);
                }

                uint32_t pal[4];
                {
                    const int c0 = (2*pc)*8 + 2*tg;
                    const int c1 = c0 + 8;
                    uint32_t ba = (uint32_t)(u0 >> c0) & 3u;
                    uint32_t bb = (uint32_t)(u1 >> c0) & 3u;
                    uint32_t bc = (uint32_t)(u0 >> c1) & 3u;
                    uint32_t bd = (uint32_t)(u1 >> c1) & 3u;
                    uint32_t ma = ((ba & 1u) ? 0x0000FFFFu : 0u) | ((ba & 2u) ? 0xFFFF0000u : 0u);
                    uint32_t mb = ((bb & 1u) ? 0x0000FFFFu : 0u) | ((bb & 2u) ? 0xFFFF0000u : 0u);
                    uint32_t mc = ((bc & 1u) ? 0x0000FFFFu : 0u) | ((bc & 2u) ? 0xFFFF0000u : 0u);
                    uint32_t md = ((bd & 1u) ? 0x0000FFFFu : 0u) | ((bd & 2u) ? 0xFFFF0000u : 0u);
                    pal[0] = ex2h2(packh2(s0[0], s0[1])) & ma;
                    pal[1] = ex2h2(packh2(s0[2], s0[3])) & mb;
                    pal[2] = ex2h2(packh2(s1[0], s1[1])) & mc;
                    pal[3] = ex2h2(packh2(s1[2], s1[3])) & md;
                }

                mma16816(lacc, pal, ONESH2, ONESH2);
                #pragma unroll
                for (int p2 = 0; p2 < 4; p2++) {
                    int r = pc*16 + vrow;
                    uint32_t cc = p2*2 + vsel;
                    uint32_t t4[4];
                    ldsm4t(t4, Vst + r*128 + ((cc ^ (r&7)) << 4));
                    mma16816(oacc[2*p2],   pal, t4[0], t4[1]);
                    mma16816(oacc[2*p2+1], pal, t4[2], t4[3]);
                }
            }
        }
    }
#undef AI

    const float inv0 = 1.f / lacc[0];
    const float inv1 = 1.f / lacc[2];
    __half* Ob = O + (size_t)(b*LL + q0)*FEA + h*DKH;
    #pragma unroll
    for (int nf = 0; nf < 8; nf++) {
        int col = nf*8 + 2*tg;
        *(__half2*)(Ob + (size_t)row*FEA + col) =
            __floats2half2_rn(oacc[nf][0]*inv0, oacc[nf][1]*inv0);
        *(__half2*)(Ob + (size_t)(row+8)*FEA + col) =
            __floats2half2_rn(oacc[nf][2]*inv1, oacc[nf][3]*inv1);
    }
}

// ---------------------------------------------------------------------------
// LayerNorm (512), 2 rows per CTA. DUAL: also write fp16.
// ---------------------------------------------------------------------------
template<int DUAL>
__global__ __launch_bounds__(256)
void ln_kernel(const float* __restrict__ x, const float* __restrict__ g,
               const float* __restrict__ b, float* __restrict__ y,
               __half* __restrict__ yh)
{
    const int half = threadIdx.x >> 7;
    const int row  = blockIdx.x * 2 + half;
    const int t    = threadIdx.x & 127;
    float4 v = ((const float4*)(x + (size_t)row*FEA))[t];
    float s  = v.x + v.y + v.z + v.w;
    float sq = v.x*v.x + v.y*v.y + v.z*v.z + v.w*v.w;

    __shared__ float ssum[2][4], ssq[2][4];
    #pragma unroll
    for (int off = 16; off; off >>= 1) {
        s  += __shfl_down_sync(0xffffffffu, s,  off);
        sq += __shfl_down_sync(0xffffffffu, sq, off);
    }
    if ((t & 31) == 0) { ssum[half][t>>5] = s; ssq[half][t>>5] = sq; }
    __syncthreads();
    const float tot  = ssum[half][0]+ssum[half][1]+ssum[half][2]+ssum[half][3];
    const float totq = ssq[half][0]+ssq[half][1]+ssq[half][2]+ssq[half][3];
    const float mu  = tot * (1.f/512.f);
    const float var = totq * (1.f/512.f) - mu*mu;
    const float inv = rsqrtf(var + 1e-5f);

    float4 gg = ((const float4*)g)[t];
    float4 bb = ((const float4*)b)[t];
    float4 o;
    o.x = (v.x-mu)*inv*gg.x + bb.x;
    o.y = (v.y-mu)*inv*gg.y + bb.y;
    o.z = (v.z-mu)*inv*gg.z + bb.z;
    o.w = (v.w-mu)*inv*gg.w + bb.w;
    ((float4*)(y + (size_t)row*FEA))[t] = o;
    if (DUAL) {
        ((__half2*)(yh + (size_t)row*FEA))[2*t]   = __floats2half2_rn(o.x, o.y);
        ((__half2*)(yh + (size_t)row*FEA))[2*t+1] = __floats2half2_rn(o.z, o.w);
    }
}

// ---------------------------------------------------------------------------
// Launch
// ---------------------------------------------------------------------------
extern "C" void kernel_launch(void* const* d_in, const int* in_sizes, int n_in,
                              void* d_out, int out_size)
{
    const float* qx   = (const float*)d_in[0];
    const float* kx   = (const float*)d_in[1];
    const float* vx   = (const float*)d_in[2];
    const int*   mpad = (const int*)  d_in[3];
    const float* wq   = (const float*)d_in[4];
    const float* bq   = (const float*)d_in[5];
    const float* wk   = (const float*)d_in[6];
    const float* bk   = (const float*)d_in[7];
    const float* wv   = (const float*)d_in[8];
    const float* bv   = (const float*)d_in[9];
    const float* wo   = (const float*)d_in[10];
    const float* bo   = (const float*)d_in[11];
    const float* w1   = (const float*)d_in[12];
    const float* b1   = (const float*)d_in[13];
    const float* w2   = (const float*)d_in[14];
    const float* b2   = (const float*)d_in[15];
    const float* ln1g = (const float*)d_in[16];
    const float* ln1b = (const float*)d_in[17];
    const float* ln2g = (const float*)d_in[18];
    const float* ln2b = (const float*)d_in[19];
    float* out = (float*)d_out;

    float *dz, *dzn32, *df;
    uint32_t* dmb;
    __half *hxin, *hqkv, *hwqkv, *hao, *hzn, *hh, *hwo, *hw1, *hw2;
    cudaGetSymbolAddress((void**)&dz,    g_z);
    cudaGetSymbolAddress((void**)&dzn32, g_zn32);
    cudaGetSymbolAddress((void**)&df,    g_f);
    cudaGetSymbolAddress((void**)&dmb,   g_mb);
    cudaGetSymbolAddress((void**)&hxin,  g_xin16);
    cudaGetSymbolAddress((void**)&hqkv,  g_qkv16);
    cudaGetSymbolAddress((void**)&hwqkv, g_wqkv16);
    cudaGetSymbolAddress((void**)&hao,   g_ao16);
    cudaGetSymbolAddress((void**)&hzn,   g_zn16);
    cudaGetSymbolAddress((void**)&hh,    g_h16);
    cudaGetSymbolAddress((void**)&hwo,   g_wo16);
    cudaGetSymbolAddress((void**)&hw1,   g_w116);
    cudaGetSymbolAddress((void**)&hw2,   g_w216);

    static cudaStream_t sB = nullptr, sC = nullptr;
    static cudaEvent_t eFork = nullptr, eMask = nullptr, eW = nullptr;
    if (!sB) {
        cudaStreamCreateWithFlags(&sB, cudaStreamNonBlocking);
        cudaStreamCreateWithFlags(&sC, cudaStreamNonBlocking);
        cudaEventCreateWithFlags(&eFork, cudaEventDisableTiming);
        cudaEventCreateWithFlags(&eMask, cudaEventDisableTiming);
        cudaEventCreateWithFlags(&eW,    cudaEventDisableTiming);
    }

    cudaFuncSetAttribute(gemm_f16<0,1,1>, cudaFuncAttributeMaxDynamicSharedMemorySize, GEMM_SMEM_BYTES);
    cudaFuncSetAttribute(gemm_f16<1,1,0>, cudaFuncAttributeMaxDynamicSharedMemorySize, GEMM_SMEM_BYTES);
    cudaFuncSetAttribute(gemm_f16<2,0,0>, cudaFuncAttributeMaxDynamicSharedMemorySize, GEMM_SMEM_BYTES);
    cudaFuncSetAttribute(attn_f16, cudaFuncAttributeMaxDynamicSharedMemorySize, ATT_SMEM_BYTES);

    dim3 blkG(512);
    dim3 gProj(FEA/128, MM/128);
    dim3 gProj3(FEA/128, MM/128, 3);
    dim3 gFfn1(HID/128, MM/128);
    dim3 gAttn(LL/128, NH, BB);

    Ptr3f none = {{nullptr, nullptr, nullptr}};
    Ptr3f qkvbias = {{bq, bk, bv}};
    ActJobs aj = {qx, kx, vx, hxin, wq, wk, wv, hwqkv};
    WJobs wj = {wo, w1, w2, hwo, hw1, hw2};

    cudaEventRecord(eFork, 0);
    cudaStreamWaitEvent(sB, eFork, 0);
    cudaStreamWaitEvent(sC, eFork, 0);

    pre_mask<<<NB_MASK, 256, 0, sB>>>((const int4*)mpad, dmb);
    cudaEventRecord(eMask, sB);

    pre_wflat<<<NB_WFLAT, 256, 0, sC>>>(wj);
    cudaEventRecord(eW, sC);

    pre_acts<<<NB_ACT + NB_WQKV, 256>>>(aj);
    gemm_f16<0,1,1><<<gProj3, blkG, GEMM_SMEM_BYTES>>>(hxin, hwqkv, nullptr, nullptr,
                                                       hqkv, MM, FEA, FEA, qkvbias);

    cudaStreamWaitEvent(0, eMask, 0);
    attn_f16<<<gAttn, 256, ATT_SMEM_BYTES>>>(hqkv, hqkv + (size_t)MM*FEA,
                                             hqkv + (size_t)2*MM*FEA, dmb, hao);

    cudaStreamWaitEvent(0, eW, 0);
    gemm_f16<2,0,0><<<gProj, blkG, GEMM_SMEM_BYTES>>>(hao, hwo, bo, vx, dz, MM, FEA, FEA, none);

    ln_kernel<1><<<MM/2, 256>>>(dz, ln1g, ln1b, dzn32, hzn);

    gemm_f16<1,1,0><<<gFfn1, blkG, GEMM_SMEM_BYTES>>>(hzn, hw1, b1, nullptr, hh, MM, HID, FEA, none);
    gemm_f16<2,0,0><<<gProj, blkG, GEMM_SMEM_BYTES>>>(hh, hw2, b2, dzn32, df, MM, FEA, HID, none);

    ln_kernel<0><<<MM/2, 256>>>(df, ln2g, ln2b, out, nullptr);
}

// round 17
// speedup vs baseline: 1.1281x; 1.1281x over previous
#include <cuda_runtime.h>
#include <cuda_fp16.h>
#include <math.h>
#include <stdint.h>

#define FEA 512
#define DKH 64
#define NH  8
#define BB  4
#define LL  2048
#define MM  (BB*LL)          // 8192
#define MH  (MM/2)           // 4096 rows per chain
#define HID (4*FEA)          // 2048

// ---------------------------------------------------------------------------
// Scratch
// ---------------------------------------------------------------------------
__device__ float g_z   [MM*FEA];
__device__ float g_zn32[MM*FEA];
__device__ float g_f   [MM*FEA];
__device__ uint32_t g_mb[BB*LL*(LL/32)];

__device__ __align__(256) __half g_xin16 [3*MM*FEA];
__device__ __align__(256) __half g_qkv16 [3*MM*FEA];
__device__ __align__(256) __half g_wqkv16[3*FEA*FEA];
__device__ __align__(256) __half g_ao16[MM*FEA];
__device__ __align__(256) __half g_zn16[MM*FEA];
__device__ __align__(256) __half g_h16 [MM*HID];
__device__ __align__(256) __half g_wo16[FEA*FEA];
__device__ __align__(256) __half g_w116[FEA*HID];
__device__ __align__(256) __half g_w216[HID*FEA];

struct Ptr3f { const float* p[3]; };
struct ActJobs {   // half-batch activation conversion
    const float* a0; const float* a1; const float* a2; __half* xin;
};
struct WJobs {
    const float* wo; const float* w1; const float* w2;
    __half* hwo; __half* hw1; __half* hw2;
};

// per-chain segmentation
#define NWORDSH  (2*LL*LL/32)                // 262144 mask words per chain
#define NB_MASKH (NWORDSH/256)               // 1024
#define NA4H     (MH*FEA/4)                  // 524288 float4 per tensor half
#define NB_ACTH  (3*NA4H/1024)               // 1536
#define NW4      (FEA*FEA/4)
#define NB_WQKV  (3*NW4/1024)                // 192
#define NF0      (FEA*FEA/4)
#define NF01     (FEA*FEA/4 + FEA*HID/4)
#define NFTOT    (FEA*FEA/4 + FEA*HID/4 + HID*FEA/4)
#define NB_WFLAT (NFTOT/1024)

// log2e / sqrt(dk): folded into Q at the projection epilogue
#define QSC 0.18033688011112042f

// ---------------------------------------------------------------------------
// helpers
// ---------------------------------------------------------------------------
__device__ __forceinline__ uint32_t cvta_s(const void* p) {
    uint32_t a;
    asm("{ .reg .u64 t; cvta.to.shared.u64 t, %1; cvt.u32.u64 %0, t; }"
        : "=r"(a) : "l"(p));
    return a;
}
__device__ __forceinline__ void cp16(uint32_t dst, const void* src) {
    asm volatile("cp.async.cg.shared.global [%0], [%1], 16;" :: "r"(dst), "l"(src));
}
#define CP_COMMIT() asm volatile("cp.async.commit_group;")
#define CP_WAIT(n)  asm volatile("cp.async.wait_group %0;" :: "n"(n))

__device__ __forceinline__ void ldsm4(uint32_t r[4], uint32_t addr) {
    asm volatile("ldmatrix.sync.aligned.m8n8.x4.shared.b16 {%0,%1,%2,%3}, [%4];"
        : "=r"(r[0]), "=r"(r[1]), "=r"(r[2]), "=r"(r[3]) : "r"(addr));
}
__device__ __forceinline__ void ldsm4t(uint32_t r[4], uint32_t addr) {
    asm volatile("ldmatrix.sync.aligned.m8n8.x4.trans.shared.b16 {%0,%1,%2,%3}, [%4];"
        : "=r"(r[0]), "=r"(r[1]), "=r"(r[2]), "=r"(r[3]) : "r"(addr));
}
__device__ __forceinline__ void mma16816(float c[4], const uint32_t a[4],
                                         uint32_t b0, uint32_t b1) {
    asm volatile(
        "mma.sync.aligned.m16n8k16.row.col.f32.f16.f16.f32 "
        "{%0,%1,%2,%3}, {%4,%5,%6,%7}, {%8,%9}, {%0,%1,%2,%3};"
        : "+f"(c[0]), "+f"(c[1]), "+f"(c[2]), "+f"(c[3])
        : "r"(a[0]), "r"(a[1]), "r"(a[2]), "r"(a[3]), "r"(b0), "r"(b1));
}
__device__ __forceinline__ uint32_t ex2h2(uint32_t x) {
    uint32_t r;
    asm("ex2.approx.f16x2 %0, %1;" : "=r"(r) : "r"(x));
    return r;
}
__device__ __forceinline__ uint32_t packh2(float lo, float hi) {
    __half2 h = __floats2half2_rn(lo, hi);
    return *reinterpret_cast<uint32_t*>(&h);
}
__device__ __forceinline__ void f2h_one(const float* s, __half* d, int off) {
    float4 v = ((const float4*)s)[off];
    ((__half2*)d)[2*off]   = __floats2half2_rn(v.x, v.y);
    ((__half2*)d)[2*off+1] = __floats2half2_rn(v.z, v.w);
}

// ---------------------------------------------------------------------------
// pre-pass kernels
// ---------------------------------------------------------------------------
__global__ __launch_bounds__(256)
void pre_mask(const int4* __restrict__ mask, uint32_t* __restrict__ mbits)
{
    int T = blockIdx.x * 256 + threadIdx.x;
    const int4* p = mask + (size_t)T * 8;
    uint32_t w = 0;
    #pragma unroll
    for (int k = 0; k < 8; k++) {
        int4 v = p[k];
        uint32_t n = umin((uint32_t)v.x, 1u)
                   | (umin((uint32_t)v.y, 1u) << 1)
                   | (umin((uint32_t)v.z, 1u) << 2)
                   | (umin((uint32_t)v.w, 1u) << 3);
        w |= n << (k * 4);
    }
    mbits[T] = w;
}

// activations for one chain: 3 tensors x NA4H float4
__global__ __launch_bounds__(256)
void pre_acts(ActJobs j)
{
    const int bid = blockIdx.x, tid = threadIdx.x;
    int base = bid * 1024;
    int z = base / NA4H;
    const float* s = z == 0 ? j.a0 : (z == 1 ? j.a1 : j.a2);
    __half* d = j.xin + (size_t)z * MM * FEA / 4 * 4;   // z-stride over FULL tensor
    int lb = base - z * NA4H;
    #pragma unroll
    for (int k = 0; k < 4; k++)
        f2h_one(s, d, lb + tid + k * 256);
}

// qkv weights (shared): 3 x NW4
__global__ __launch_bounds__(256)
void pre_wqkv(Ptr3f w, __half* __restrict__ wqkv)
{
    const int bid = blockIdx.x, tid = threadIdx.x;
    int base = bid * 1024;
    int z = base / NW4;
    const float* s = w.p[z];
    __half* d = wqkv + (size_t)z * NW4 * 4;
    int lb = base - z * NW4;
    #pragma unroll
    for (int k = 0; k < 4; k++)
        f2h_one(s, d, lb + tid + k * 256);
}

__global__ __launch_bounds__(256)
void pre_wflat(WJobs j)
{
    const int tid = threadIdx.x;
    int base = blockIdx.x * 1024;
    const float* s; __half* d; int lb;
    if (base < NF0)       { s = j.wo; d = j.hwo; lb = base; }
    else if (base < NF01) { s = j.w1; d = j.hw1; lb = base - NF0; }
    else                  { s = j.w2; d = j.hw2; lb = base - NF01; }
    #pragma unroll
    for (int k = 0; k < 4; k++)
        f2h_one(s, d, lb + tid + k * 256);
}

// ---------------------------------------------------------------------------
// fp16 GEMM (R15 config): 3-stage cp.async + ldmatrix, BK=64, 256 thr,
// warp tile 64x32. TRIPLE: z-stride zstr for A and C (weights full stride).
// ---------------------------------------------------------------------------
#define GEMM_SMEM_BYTES (3*32768)

template<int EPI, int OUTH, int TRIPLE>
__global__ __launch_bounds__(256, 2)
void gemm_f16(const __half* __restrict__ A, const __half* __restrict__ W,
              const float* __restrict__ bias, const float* __restrict__ res,
              void* __restrict__ Cv, int M, int N, int K, Ptr3f b3, size_t zstr)
{
    extern __shared__ __align__(16) uint8_t smg[];
    const uint32_t sT = cvta_s(smg);

    __half* Ch = (__half*)Cv;
    float*  Cf = (float*)Cv;
    float oscale = 1.0f;
    if (TRIPLE) {
        const int z = blockIdx.z;
        A += (size_t)z * zstr;
        W += (size_t)z * K * N;
        Ch += (size_t)z * zstr;
        bias = b3.p[z];
        if (z == 0) oscale = QSC;
    }

    const int tid = threadIdx.x, lane = tid & 31, wid = tid >> 5;
    const int warpRow = wid & 1, warpCol = wid >> 1;
    const int m0 = blockIdx.y * 128, n0 = blockIdx.x * 128;
    const int g = lane >> 2, tg = lane & 3;

    const int KT = K >> 6;
    float acc[4][4][4] = {};

#define GI(st, ck) do { const int k0_ = (ck) << 6;                                \
    _Pragma("unroll")                                                             \
    for (int i_ = 0; i_ < 4; i_++) {                                              \
        int ia_ = tid + i_ * 256;                                                 \
        int ra_ = ia_ >> 3, ca_ = ia_ & 7;                                        \
        cp16(sT + (st)*32768 + ra_*128 + (uint32_t)((ca_ ^ (ra_ & 7)) << 4),      \
             A + (size_t)(m0 + ra_)*K + k0_ + ca_*8);                             \
        int rb_ = ia_ >> 4, cb_ = ia_ & 15;                                       \
        cp16(sT + (st)*32768 + 16384 + rb_*256 + (uint32_t)((cb_ ^ (rb_ & 7)) << 4), \
             W + (size_t)(k0_ + rb_)*N + n0 + cb_*8);                             \
    } } while (0)

    GI(0, 0); CP_COMMIT();
    GI(1, 1); CP_COMMIT();

    const int arow = warpRow*64 + (lane & 15);
    const int alo  = lane >> 4;
    const int brow = lane & 15;
    const int bccb = warpCol*4 + (lane >> 4);

    int cur = 0;
    for (int kt = 0; kt < KT; kt++) {
        CP_WAIT(1);
        __syncthreads();
        if (kt + 2 < KT) { int st = cur >= 1 ? cur - 1 : 2; GI(st, kt + 2); }
        CP_COMMIT();
        const uint32_t Ast = sT + cur * 32768;
        const uint32_t Bst = Ast + 16384;

        #pragma unroll
        for (int kc = 0; kc < 4; kc++) {
            uint32_t af[4][4];
            #pragma unroll
            for (int mf = 0; mf < 4; mf++) {
                int r = arow + mf * 16;
                ldsm4(af[mf], Ast + r*128 + (((kc*2 + alo) ^ (r & 7)) << 4));
            }
            uint32_t bf[4][2];
            #pragma unroll
            for (int p = 0; p < 2; p++) {
                int r = kc*16 + brow;
                uint32_t cc = bccb + p*2;
                uint32_t t4[4];
                ldsm4t(t4, Bst + r*256 + ((cc ^ (r & 7)) << 4));
                bf[2*p][0] = t4[0]; bf[2*p][1] = t4[1];
                bf[2*p+1][0] = t4[2]; bf[2*p+1][1] = t4[3];
            }
            #pragma unroll
            for (int mf = 0; mf < 4; mf++)
                #pragma unroll
                for (int nf = 0; nf < 4; nf++)
                    mma16816(acc[mf][nf], af[mf], bf[nf][0], bf[nf][1]);
        }
        cur = cur < 2 ? cur + 1 : 0;
    }
#undef GI

    #pragma unroll
    for (int mf = 0; mf < 4; mf++) {
        int row = m0 + warpRow*64 + mf*16 + g;
        #pragma unroll
        for (int nf = 0; nf < 4; nf++) {
            int col = n0 + warpCol*32 + nf*8 + 2*tg;
            float2 bi = *(const float2*)&bias[col];
            float o0 = acc[mf][nf][0] + bi.x;
            float o1 = acc[mf][nf][1] + bi.y;
            float o2 = acc[mf][nf][2] + bi.x;
            float o3 = acc[mf][nf][3] + bi.y;
            if (EPI == 1) {
                o0 = 0.5f*o0*(1.f+erff(o0*0.70710678118654752f));
                o1 = 0.5f*o1*(1.f+erff(o1*0.70710678118654752f));
                o2 = 0.5f*o2*(1.f+erff(o2*0.70710678118654752f));
                o3 = 0.5f*o3*(1.f+erff(o3*0.70710678118654752f));
            } else if (EPI == 2) {
                float2 r0 = *(const float2*)&res[(size_t)row*N + col];
                float2 r1 = *(const float2*)&res[(size_t)(row+8)*N + col];
                o0 += r0.x; o1 += r0.y; o2 += r1.x; o3 += r1.y;
            }
            if (TRIPLE) { o0 *= oscale; o1 *= oscale; o2 *= oscale; o3 *= oscale; }
            if (OUTH) {
                *(__half2*)&Ch[(size_t)row*N + col]     = __floats2half2_rn(o0, o1);
                *(__half2*)&Ch[(size_t)(row+8)*N + col] = __floats2half2_rn(o2, o3);
            } else {
                float2 w0 = {o0, o1}, w1 = {o2, o3};
                *(float2*)&Cf[(size_t)row*N + col]     = w0;
                *(float2*)&Cf[(size_t)(row+8)*N + col] = w1;
            }
        }
    }
}

// ---------------------------------------------------------------------------
// fp16 flash attention — R15 (Q pre-scaled, shift-free softmax). Pointers
// pre-offset per chain; blockIdx.z is the LOCAL batch.
// ---------------------------------------------------------------------------
#define ATT_SMEM_BYTES (16384 + 2*32768)
#define ONESH2 0x3C003C00u

__global__ __launch_bounds__(256, 2)
void attn_f16(const __half* __restrict__ Q, const __half* __restrict__ Kg,
              const __half* __restrict__ Vg, const uint32_t* __restrict__ mbits,
              __half* __restrict__ O)
{
    extern __shared__ __align__(16) uint8_t smb[];
    const uint32_t sQ  = cvta_s(smb);
    const uint32_t sKV = sQ + 16384;

    const int q0 = blockIdx.x * 128;
    const int h  = blockIdx.y;
    const int b  = blockIdx.z;
    const int tid = threadIdx.x, lane = tid & 31, wid = tid >> 5;
    const int g = lane >> 2, tg = lane & 3;
    const int row = wid*16 + g;

    const __half* Qb = Q + (size_t)(b*LL + q0)*FEA + h*DKH;
    const __half* Kb = Kg + (size_t)(b*LL)*FEA + h*DKH;
    const __half* Vb = Vg + (size_t)(b*LL)*FEA + h*DKH;

    #pragma unroll
    for (int i = 0; i < 4; i++) {
        int idx = tid + i*256;
        int r = idx >> 3, c = idx & 7;
        cp16(sQ + r*128 + ((c ^ (r&7)) << 4), Qb + (size_t)r*FEA + c*8);
    }
    CP_COMMIT();

#define AI(st, k0_) do { _Pragma("unroll")                                      \
    for (int i_ = 0; i_ < 4; i_++) {                                            \
        int idx_ = tid + i_*256;                                                \
        int r_ = idx_ >> 3, c_ = idx_ & 7;                                      \
        uint32_t off_ = r_*128 + ((c_ ^ (r_&7)) << 4);                          \
        cp16(sKV + (st)*32768 + off_,         Kb + (size_t)((k0_)+r_)*FEA + c_*8); \
        cp16(sKV + (st)*32768 + 16384 + off_, Vb + (size_t)((k0_)+r_)*FEA + c_*8); \
    } } while (0)

    AI(0, 0); CP_COMMIT();
    CP_WAIT(1);
    __syncthreads();

    uint32_t qf[4][4];
    {
        int r = wid*16 + (lane & 15);
        int lo = lane >> 4;
        #pragma unroll
        for (int kc = 0; kc < 4; kc++)
            ldsm4(qf[kc], sQ + r*128 + (((kc*2 + lo) ^ (r&7)) << 4));
    }

    float oacc[8][4] = {};
    float lacc[4] = {};
    const uint32_t* mb0 = mbits + (size_t)(b*LL + q0 + row) * (LL/32);
    const uint32_t* mb1 = mb0 + 8 * (LL/32);

    const int krow = ((lane>>4)<<3) | (lane & 7);
    const int ksel = (lane>>3) & 1;
    const int vrow = (((lane>>3)&1)<<3) | (lane&7);
    const int vsel = lane >> 4;

    for (int t = 0; t < LL/128; t++) {
        uint4 w0 = *(const uint4*)(mb0 + 4*t);
        uint4 w1 = *(const uint4*)(mb1 + 4*t);

        CP_WAIT(0);
        __syncthreads();
        if (t + 1 < LL/128) AI((t+1) & 1, (t+1)*128);
        CP_COMMIT();
        const uint32_t stBase = sKV + (t&1)*32768;

        #pragma unroll
        for (int hh = 0; hh < 2; hh++) {
            const uint32_t Kst = stBase + hh*8192;
            const uint32_t Vst = stBase + 16384 + hh*8192;
            const uint64_t u0 = hh ? ((uint64_t)w0.z | ((uint64_t)w0.w << 32))
                                   : ((uint64_t)w0.x | ((uint64_t)w0.y << 32));
            const uint64_t u1 = hh ? ((uint64_t)w1.z | ((uint64_t)w1.w << 32))
                                   : ((uint64_t)w1.x | ((uint64_t)w1.y << 32));

            #pragma unroll
            for (int pc = 0; pc < 4; pc++) {
                float s0[4] = {}, s1[4] = {};
                #pragma unroll
                for (int kc = 0; kc < 4; kc++) {
                    int r = pc*16 + krow;
                    uint32_t cc = kc*2 + ksel;
                    uint32_t t4[4];
                    ldsm4(t4, Kst + r*128 + ((cc ^ (r&7)) << 4));
                    mma16816(s0, qf[kc], t4[0], t4[1]);
                    mma16816(s1, qf[kc], t4[2], t4[3]);
                }

                uint32_t pal[4];
                {
                    const int c0 = (2*pc)*8 + 2*tg;
                    const int c1 = c0 + 8;
                    uint32_t ba = (uint32_t)(u0 >> c0) & 3u;
                    uint32_t bb = (uint32_t)(u1 >> c0) & 3u;
                    uint32_t bc = (uint32_t)(u0 >> c1) & 3u;
                    uint32_t bd = (uint32_t)(u1 >> c1) & 3u;
                    uint32_t ma = ((ba & 1u) ? 0x0000FFFFu : 0u) | ((ba & 2u) ? 0xFFFF0000u : 0u);
                    uint32_t mb = ((bb & 1u) ? 0x0000FFFFu : 0u) | ((bb & 2u) ? 0xFFFF0000u : 0u);
                    uint32_t mc = ((bc & 1u) ? 0x0000FFFFu : 0u) | ((bc & 2u) ? 0xFFFF0000u : 0u);
                    uint32_t md = ((bd & 1u) ? 0x0000FFFFu : 0u) | ((bd & 2u) ? 0xFFFF0000u : 0u);
                    pal[0] = ex2h2(packh2(s0[0], s0[1])) & ma;
                    pal[1] = ex2h2(packh2(s0[2], s0[3])) & mb;
                    pal[2] = ex2h2(packh2(s1[0], s1[1])) & mc;
                    pal[3] = ex2h2(packh2(s1[2], s1[3])) & md;
                }

                mma16816(lacc, pal, ONESH2, ONESH2);
                #pragma unroll
                for (int p2 = 0; p2 < 4; p2++) {
                    int r = pc*16 + vrow;
                    uint32_t cc = p2*2 + vsel;
                    uint32_t t4[4];
                    ldsm4t(t4, Vst + r*128 + ((cc ^ (r&7)) << 4));
                    mma16816(oacc[2*p2],   pal, t4[0], t4[1]);
                    mma16816(oacc[2*p2+1], pal, t4[2], t4[3]);
                }
            }
        }
    }
#undef AI

    const float inv0 = 1.f / lacc[0];
    const float inv1 = 1.f / lacc[2];
    __half* Ob = O + (size_t)(b*LL + q0)*FEA + h*DKH;
    #pragma unroll
    for (int nf = 0; nf < 8; nf++) {
        int col = nf*8 + 2*tg;
        *(__half2*)(Ob + (size_t)row*FEA + col) =
            __floats2half2_rn(oacc[nf][0]*inv0, oacc[nf][1]*inv0);
        *(__half2*)(Ob + (size_t)(row+8)*FEA + col) =
            __floats2half2_rn(oacc[nf][2]*inv1, oacc[nf][3]*inv1);
    }
}

// ---------------------------------------------------------------------------
// LayerNorm (512), 2 rows per CTA. DUAL: also write fp16.
// ---------------------------------------------------------------------------
template<int DUAL>
__global__ __launch_bounds__(256)
void ln_kernel(const float* __restrict__ x, const float* __restrict__ g,
               const float* __restrict__ b, float* __restrict__ y,
               __half* __restrict__ yh)
{
    const int half = threadIdx.x >> 7;
    const int row  = blockIdx.x * 2 + half;
    const int t    = threadIdx.x & 127;
    float4 v = ((const float4*)(x + (size_t)row*FEA))[t];
    float s  = v.x + v.y + v.z + v.w;
    float sq = v.x*v.x + v.y*v.y + v.z*v.z + v.w*v.w;

    __shared__ float ssum[2][4], ssq[2][4];
    #pragma unroll
    for (int off = 16; off; off >>= 1) {
        s  += __shfl_down_sync(0xffffffffu, s,  off);
        sq += __shfl_down_sync(0xffffffffu, sq, off);
    }
    if ((t & 31) == 0) { ssum[half][t>>5] = s; ssq[half][t>>5] = sq; }
    __syncthreads();
    const float tot  = ssum[half][0]+ssum[half][1]+ssum[half][2]+ssum[half][3];
    const float totq = ssq[half][0]+ssq[half][1]+ssq[half][2]+ssq[half][3];
    const float mu  = tot * (1.f/512.f);
    const float var = totq * (1.f/512.f) - mu*mu;
    const float inv = rsqrtf(var + 1e-5f);

    float4 gg = ((const float4*)g)[t];
    float4 bb = ((const float4*)b)[t];
    float4 o;
    o.x = (v.x-mu)*inv*gg.x + bb.x;
    o.y = (v.y-mu)*inv*gg.y + bb.y;
    o.z = (v.z-mu)*inv*gg.z + bb.z;
    o.w = (v.w-mu)*inv*gg.w + bb.w;
    ((float4*)(y + (size_t)row*FEA))[t] = o;
    if (DUAL) {
        ((__half2*)(yh + (size_t)row*FEA))[2*t]   = __floats2half2_rn(o.x, o.y);
        ((__half2*)(yh + (size_t)row*FEA))[2*t+1] = __floats2half2_rn(o.z, o.w);
    }
}

// ---------------------------------------------------------------------------
// Launch — two independent half-batch chains on two streams
// ---------------------------------------------------------------------------
extern "C" void kernel_launch(void* const* d_in, const int* in_sizes, int n_in,
                              void* d_out, int out_size)
{
    const float* qx   = (const float*)d_in[0];
    const float* kx   = (const float*)d_in[1];
    const float* vx   = (const float*)d_in[2];
    const int*   mpad = (const int*)  d_in[3];
    const float* wq   = (const float*)d_in[4];
    const float* bq   = (const float*)d_in[5];
    const float* wk   = (const float*)d_in[6];
    const float* bk   = (const float*)d_in[7];
    const float* wv   = (const float*)d_in[8];
    const float* bv   = (const float*)d_in[9];
    const float* wo   = (const float*)d_in[10];
    const float* bo   = (const float*)d_in[11];
    const float* w1   = (const float*)d_in[12];
    const float* b1   = (const float*)d_in[13];
    const float* w2   = (const float*)d_in[14];
    const float* b2   = (const float*)d_in[15];
    const float* ln1g = (const float*)d_in[16];
    const float* ln1b = (const float*)d_in[17];
    const float* ln2g = (const float*)d_in[18];
    const float* ln2b = (const float*)d_in[19];
    float* out = (float*)d_out;

    float *dz, *dzn32, *df;
    uint32_t* dmb;
    __half *hxin, *hqkv, *hwqkv, *hao, *hzn, *hh, *hwo, *hw1, *hw2;
    cudaGetSymbolAddress((void**)&dz,    g_z);
    cudaGetSymbolAddress((void**)&dzn32, g_zn32);
    cudaGetSymbolAddress((void**)&df,    g_f);
    cudaGetSymbolAddress((void**)&dmb,   g_mb);
    cudaGetSymbolAddress((void**)&hxin,  g_xin16);
    cudaGetSymbolAddress((void**)&hqkv,  g_qkv16);
    cudaGetSymbolAddress((void**)&hwqkv, g_wqkv16);
    cudaGetSymbolAddress((void**)&hao,   g_ao16);
    cudaGetSymbolAddress((void**)&hzn,   g_zn16);
    cudaGetSymbolAddress((void**)&hh,    g_h16);
    cudaGetSymbolAddress((void**)&hwo,   g_wo16);
    cudaGetSymbolAddress((void**)&hw1,   g_w116);
    cudaGetSymbolAddress((void**)&hw2,   g_w216);

    static cudaStream_t sB = nullptr, sC = nullptr;
    static cudaEvent_t eFork = nullptr, eWq = nullptr, eW = nullptr, eB = nullptr;
    if (!sB) {
        cudaStreamCreateWithFlags(&sB, cudaStreamNonBlocking);
        cudaStreamCreateWithFlags(&sC, cudaStreamNonBlocking);
        cudaEventCreateWithFlags(&eFork, cudaEventDisableTiming);
        cudaEventCreateWithFlags(&eWq,   cudaEventDisableTiming);
        cudaEventCreateWithFlags(&eW,    cudaEventDisableTiming);
        cudaEventCreateWithFlags(&eB,    cudaEventDisableTiming);
    }

    cudaFuncSetAttribute(gemm_f16<0,1,1>, cudaFuncAttributeMaxDynamicSharedMemorySize, GEMM_SMEM_BYTES);
    cudaFuncSetAttribute(gemm_f16<1,1,0>, cudaFuncAttributeMaxDynamicSharedMemorySize, GEMM_SMEM_BYTES);
    cudaFuncSetAttribute(gemm_f16<2,0,0>, cudaFuncAttributeMaxDynamicSharedMemorySize, GEMM_SMEM_BYTES);
    cudaFuncSetAttribute(attn_f16, cudaFuncAttributeMaxDynamicSharedMemorySize, ATT_SMEM_BYTES);

    Ptr3f none = {{nullptr, nullptr, nullptr}};
    Ptr3f qkvbias = {{bq, bk, bv}};
    Ptr3f wsrc = {{wq, wk, wv}};
    WJobs wj = {wo, w1, w2, hwo, hw1, hw2};

    // fork
    cudaEventRecord(eFork, 0);
    cudaStreamWaitEvent(sB, eFork, 0);
    cudaStreamWaitEvent(sC, eFork, 0);

    // stream C: weight conversions (shared by both chains)
    pre_wqkv<<<NB_WQKV, 256, 0, sC>>>(wsrc, hwqkv);
    cudaEventRecord(eWq, sC);
    pre_wflat<<<NB_WFLAT, 256, 0, sC>>>(wj);
    cudaEventRecord(eW, sC);

    // per-chain launcher
    dim3 gProjH(FEA/128, MH/128);          // (4, 32)
    dim3 gProj3H(FEA/128, MH/128, 3);
    dim3 gFfn1H(HID/128, MH/128);          // (16, 32)
    dim3 gAttnH(LL/128, NH, 2);

    for (int c = 0; c < 2; c++) {
        cudaStream_t s = c == 0 ? (cudaStream_t)0 : sB;
        const size_t ro  = (size_t)c * MH;            // row offset
        const size_t roF = ro * FEA;
        const size_t roH = ro * HID;
        const size_t roM = ro * (LL/32);              // mask-bit row offset

        // chain pre-passes
        pre_mask<<<NB_MASKH, 256, 0, s>>>((const int4*)(mpad + (size_t)c*2*LL*LL),
                                          dmb + (size_t)c * NWORDSH);
        ActJobs aj = {qx + roF, kx + roF, vx + roF, hxin + roF};
        pre_acts<<<NB_ACTH, 256, 0, s>>>(aj);

        // qkv projection (needs qkv weights)
        cudaStreamWaitEvent(s, eWq, 0);
        gemm_f16<0,1,1><<<gProj3H, 256, GEMM_SMEM_BYTES, s>>>(
            hxin + roF, hwqkv, nullptr, nullptr, hqkv + roF,
            MH, FEA, FEA, qkvbias, (size_t)MM*FEA);

        // attention
        attn_f16<<<gAttnH, 256, ATT_SMEM_BYTES, s>>>(
            hqkv + roF, hqkv + (size_t)MM*FEA + roF, hqkv + (size_t)2*MM*FEA + roF,
            dmb + roM * 1 /* rows*(LL/32) */, hao + roF);

        // wo + residual (needs wo/w1/w2 weights)
        cudaStreamWaitEvent(s, eW, 0);
        gemm_f16<2,0,0><<<gProjH, 256, GEMM_SMEM_BYTES, s>>>(
            hao + roF, hwo, bo, vx + roF, dz + roF, MH, FEA, FEA, none, 0);

        ln_kernel<1><<<MH/2, 256, 0, s>>>(dz + roF, ln1g, ln1b, dzn32 + roF, hzn + roF);

        gemm_f16<1,1,0><<<gFfn1H, 256, GEMM_SMEM_BYTES, s>>>(
            hzn + roF, hw1, b1, nullptr, hh + roH, MH, HID, FEA, none, 0);
        gemm_f16<2,0,0><<<gProjH, 256, GEMM_SMEM_BYTES, s>>>(
            hh + roH, hw2, b2, dzn32 + roF, df + roF, MH, FEA, HID, none, 0);

        ln_kernel<0><<<MH/2, 256, 0, s>>>(df + roF, ln2g, ln2b, out + roF, nullptr);
    }

    // join chain B into the default stream
    cudaEventRecord(eB, sB);
    cudaStreamWaitEvent(0, eB, 0);
}